// round 13
// baseline (speedup 1.0000x reference)
#include <cuda_runtime.h>

#define Bsz   4096
#define Tn    512
#define Fdim  4
#define Hn    50
#define TB    32
#define NT    256
#define ACT   200     // active threads: u(50) x bg(4); thread owns 1 unit x 8 batches

// shared byte offsets (16B aligned)
#define O_Q0HH 0                    // [k][u][4g] quads: 50*50*16 = 40000
#define O_Q1IH 40000
#define O_Q1HH 80000
#define O_Q0IH 120000               // [kf][u][4g]: 3200
#define O_BQ0  123200               // [u][4g]: 800
#define O_BQ1  124000               // 800
#define O_H0   124800               // 2 bufs x 50*144 = 14400
#define O_H1   139200               // 14400
#define O_XP   153600               // 2 bufs x [u][4g][32b] f32 = 2*25600
#define SMEM_BYTES 204800
#define HSTR   144                  // bytes per k-row (32 batches*4B + 16 pad)
#define HBUFB  7200                 // one h buffer
#define XPBUF  25600                // one xp buffer

using u64 = unsigned long long;

__device__ __forceinline__ u64 pack2(float v) {
    u64 r; unsigned i = __float_as_uint(v);
    asm("mov.b64 %0, {%1, %1};" : "=l"(r) : "r"(i));
    return r;
}
__device__ __forceinline__ u64 pack2two(float a, float b) {
    u64 r;
    asm("mov.b64 %0, {%1, %2};" : "=l"(r) : "r"(__float_as_uint(a)), "r"(__float_as_uint(b)));
    return r;
}
__device__ __forceinline__ void unpack2(u64 v, float& a, float& b) {
    unsigned lo, hi;
    asm("mov.b64 {%0, %1}, %2;" : "=r"(lo), "=r"(hi) : "l"(v));
    a = __uint_as_float(lo); b = __uint_as_float(hi);
}
__device__ __forceinline__ void ffma2(u64& d, u64 a, u64 b) {
    asm("fma.rn.f32x2 %0, %1, %2, %0;" : "+l"(d) : "l"(a), "l"(b));
}
__device__ __forceinline__ float4 lds_f4(unsigned addr) {
    float4 v;
    asm("ld.shared.v4.f32 {%0, %1, %2, %3}, [%4];"
        : "=f"(v.x), "=f"(v.y), "=f"(v.z), "=f"(v.w) : "r"(addr));
    return v;
}
__device__ __forceinline__ void lds_v2b64(u64& a, u64& b, unsigned addr) {
    asm("ld.shared.v2.b64 {%0, %1}, [%2];" : "=l"(a), "=l"(b) : "r"(addr));
}
__device__ __forceinline__ void sts_u64(unsigned addr, u64 v) {
    asm("st.shared.b64 [%0], %1;" :: "r"(addr), "l"(v));
}
__device__ __forceinline__ void sts_f32(unsigned addr, float v) {
    asm("st.shared.b32 [%0], %1;" :: "r"(addr), "f"(v));
}

// MUFU.TANH-based activations (1 MUFU each)
__device__ __forceinline__ float tanha(float x) {
    float r; asm("tanh.approx.f32 %0, %1;" : "=f"(r) : "f"(x));
    return r;
}
__device__ __forceinline__ float sigt(float x) {
    return fmaf(0.5f, tanha(0.5f * x), 0.5f);   // sigmoid via tanh identity
}

#define FMA16(A, W0, W1, W2, W3, V0, V1, V2, V3) do { \
    ffma2(A[0][0], W0, V0); ffma2(A[0][1], W0, V1); \
    ffma2(A[0][2], W0, V2); ffma2(A[0][3], W0, V3); \
    ffma2(A[1][0], W1, V0); ffma2(A[1][1], W1, V1); \
    ffma2(A[1][2], W1, V2); ffma2(A[1][3], W1, V3); \
    ffma2(A[2][0], W2, V0); ffma2(A[2][1], W2, V1); \
    ffma2(A[2][2], W2, V2); ffma2(A[2][3], W2, V3); \
    ffma2(A[3][0], W3, V0); ffma2(A[3][1], W3, V1); \
    ffma2(A[3][2], W3, V2); ffma2(A[3][3], W3, V3); \
} while (0)

// gates -> c (regs), h batch-pairs -> smem at dst
__device__ __forceinline__ void epilogue(u64 acc[4][4], float* c, unsigned dst) {
    #pragma unroll
    for (int bp = 0; bp < 4; ++bp) {
        float giA, giB, gfA, gfB, ggA, ggB, goA, goB;
        unpack2(acc[0][bp], giA, giB);
        unpack2(acc[1][bp], gfA, gfB);
        unpack2(acc[2][bp], ggA, ggB);
        unpack2(acc[3][bp], goA, goB);
        float cA = fmaf(sigt(gfA), c[2 * bp],     sigt(giA) * tanha(ggA));
        float cB = fmaf(sigt(gfB), c[2 * bp + 1], sigt(giB) * tanha(ggB));
        c[2 * bp] = cA; c[2 * bp + 1] = cB;
        sts_u64(dst + bp * 8,
                pack2two(sigt(goA) * tanha(cA), sigt(goB) * tanha(cB)));
    }
}

// layer 0 GEMV: acc initialized from xp (= bias + Wih0*x, precomputed by stager),
// then += Whh0*h0_prev
__device__ __forceinline__ void gemv_l0(u64 acc[4][4],
                                        unsigned a_xp_t, unsigned a_q0hh, unsigned a_h,
                                        unsigned u512, unsigned wq_off, unsigned hoff)
{
    #pragma unroll
    for (int g = 0; g < 4; ++g) {
        lds_v2b64(acc[g][0], acc[g][1], a_xp_t + u512 + g * 128 + hoff);
        lds_v2b64(acc[g][2], acc[g][3], a_xp_t + u512 + g * 128 + hoff + 16);
    }
    #pragma unroll 10
    for (int k = 0; k < Hn; ++k) {
        float4 w = lds_f4(a_q0hh + k * 800 + wq_off);
        u64 h01, h23, h45, h67;
        lds_v2b64(h01, h23, a_h + k * HSTR + hoff);
        lds_v2b64(h45, h67, a_h + k * HSTR + hoff + 16);
        u64 w0 = pack2(w.x), w1 = pack2(w.y), w2 = pack2(w.z), w3 = pack2(w.w);
        FMA16(acc, w0, w1, w2, w3, h01, h23, h45, h67);
    }
}

// layer 1 GEMV: acc = bias + Wih1*h0_new + Whh1*h1_prev
__device__ __forceinline__ void gemv_l1(u64 acc[4][4], const u64* bs,
                                        unsigned a_q1ih, unsigned a_q1hh,
                                        unsigned a_h0n, unsigned a_h1p,
                                        unsigned wq_off, unsigned hoff)
{
    #pragma unroll
    for (int g = 0; g < 4; ++g)
        #pragma unroll
        for (int bp = 0; bp < 4; ++bp) acc[g][bp] = bs[g];
    #pragma unroll 10
    for (int k = 0; k < Hn; ++k) {
        float4 wa = lds_f4(a_q1ih + k * 800 + wq_off);
        float4 wb = lds_f4(a_q1hh + k * 800 + wq_off);
        u64 p01, p23, p45, p67;
        lds_v2b64(p01, p23, a_h0n + k * HSTR + hoff);
        lds_v2b64(p45, p67, a_h0n + k * HSTR + hoff + 16);
        u64 q01, q23, q45, q67;
        lds_v2b64(q01, q23, a_h1p + k * HSTR + hoff);
        lds_v2b64(q45, q67, a_h1p + k * HSTR + hoff + 16);
        u64 a0 = pack2(wa.x), a1 = pack2(wa.y), a2 = pack2(wa.z), a3 = pack2(wa.w);
        u64 b0 = pack2(wb.x), b1 = pack2(wb.y), b2 = pack2(wb.z), b3 = pack2(wb.w);
        FMA16(acc, a0, a1, a2, a3, p01, p23, p45, p67);
        FMA16(acc, b0, b1, b2, b3, q01, q23, q45, q67);
    }
}

// stager: xp(u,g,b=lane) = b0[u][g] + sum_kf Wih0[u][g][kf] * x[kf]
// FMA order matches the old compute-side kf loop exactly (bit-identical results).
__device__ __forceinline__ void stage_xp(unsigned sb, float4 xv, int lane, unsigned xpbuf) {
    const unsigned a_q0ih = sb + O_Q0IH;
    const unsigned a_bq0  = sb + O_BQ0;
    const unsigned dst    = sb + O_XP + xpbuf + (unsigned)lane * 4;
    #pragma unroll 5
    for (int uu = 0; uu < Hn; ++uu) {
        float4 b  = lds_f4(a_bq0 + uu * 16);
        float4 w0 = lds_f4(a_q0ih + 0 * 800 + uu * 16);
        float4 w1 = lds_f4(a_q0ih + 1 * 800 + uu * 16);
        float4 w2 = lds_f4(a_q0ih + 2 * 800 + uu * 16);
        float4 w3 = lds_f4(a_q0ih + 3 * 800 + uu * 16);
        float gi = fmaf(w3.x, xv.w, fmaf(w2.x, xv.z, fmaf(w1.x, xv.y, fmaf(w0.x, xv.x, b.x))));
        float gf = fmaf(w3.y, xv.w, fmaf(w2.y, xv.z, fmaf(w1.y, xv.y, fmaf(w0.y, xv.x, b.y))));
        float gg = fmaf(w3.z, xv.w, fmaf(w2.z, xv.z, fmaf(w1.z, xv.y, fmaf(w0.z, xv.x, b.z))));
        float go = fmaf(w3.w, xv.w, fmaf(w2.w, xv.z, fmaf(w1.w, xv.y, fmaf(w0.w, xv.x, b.w))));
        sts_f32(dst + uu * 512 + 0,   gi);
        sts_f32(dst + uu * 512 + 128, gf);
        sts_f32(dst + uu * 512 + 256, gg);
        sts_f32(dst + uu * 512 + 384, go);
    }
}

__global__ void __launch_bounds__(NT, 1) lstm2_kernel(
    const float* __restrict__ x,
    const float* __restrict__ Wih0, const float* __restrict__ Whh0,
    const float* __restrict__ bih0, const float* __restrict__ bhh0,
    const float* __restrict__ Wih1, const float* __restrict__ Whh1,
    const float* __restrict__ bih1, const float* __restrict__ bhh1,
    const float* __restrict__ fcW,  const float* __restrict__ fcb,
    float* __restrict__ out)
{
    extern __shared__ float sm[];
    const int tid = threadIdx.x;

    // ---- stage weights as per-unit gate quads [wi,wf,wg,wo] ----
    for (int i = tid; i < Hn * Hn; i += NT) {          // i = k*50 + u
        int k = i / Hn, u = i - k * Hn;
        float* q0 = sm + (O_Q0HH / 4) + i * 4;
        q0[0] = Whh0[(      u) * Hn + k];
        q0[1] = Whh0[( 50 + u) * Hn + k];
        q0[2] = Whh0[(100 + u) * Hn + k];
        q0[3] = Whh0[(150 + u) * Hn + k];
        float* q1i = sm + (O_Q1IH / 4) + i * 4;
        q1i[0] = Wih1[(      u) * Hn + k];
        q1i[1] = Wih1[( 50 + u) * Hn + k];
        q1i[2] = Wih1[(100 + u) * Hn + k];
        q1i[3] = Wih1[(150 + u) * Hn + k];
        float* q1h = sm + (O_Q1HH / 4) + i * 4;
        q1h[0] = Whh1[(      u) * Hn + k];
        q1h[1] = Whh1[( 50 + u) * Hn + k];
        q1h[2] = Whh1[(100 + u) * Hn + k];
        q1h[3] = Whh1[(150 + u) * Hn + k];
    }
    for (int i = tid; i < Fdim * Hn; i += NT) {        // i = kf*50 + u
        int kf = i / Hn, u = i - kf * Hn;
        float* q = sm + (O_Q0IH / 4) + i * 4;
        q[0] = Wih0[(      u) * Fdim + kf];
        q[1] = Wih0[( 50 + u) * Fdim + kf];
        q[2] = Wih0[(100 + u) * Fdim + kf];
        q[3] = Wih0[(150 + u) * Fdim + kf];
    }
    for (int u = tid; u < Hn; u += NT) {
        float* b0 = sm + (O_BQ0 / 4) + u * 4;
        b0[0] = bih0[u]       + bhh0[u];
        b0[1] = bih0[50 + u]  + bhh0[50 + u];
        b0[2] = bih0[100 + u] + bhh0[100 + u];
        b0[3] = bih0[150 + u] + bhh0[150 + u];
        float* b1 = sm + (O_BQ1 / 4) + u * 4;
        b1[0] = bih1[u]       + bhh1[u];
        b1[1] = bih1[50 + u]  + bhh1[50 + u];
        b1[2] = bih1[100 + u] + bhh1[100 + u];
        b1[3] = bih1[150 + u] + bhh1[150 + u];
    }
    for (int i = tid; i < (4 * HBUFB) / 4; i += NT)    // zero the 4 h buffers
        sm[(O_H0 / 4) + i] = 0.f;
    __syncthreads();                                   // weights visible (stager needs them)

    const unsigned sb = (unsigned)__cvta_generic_to_shared(sm);
    const unsigned a_q0hh = sb + O_Q0HH;
    const unsigned a_q1ih = sb + O_Q1IH;
    const unsigned a_q1hh = sb + O_Q1HH;
    const unsigned a_h0   = sb + O_H0;
    const unsigned a_h1   = sb + O_H1;
    const unsigned a_xp   = sb + O_XP;

    // warp 7 = stager (tid 224-255, no compute slots)
    const bool xw = (tid >= 224);
    const int  xl = tid & 31;
    const float4* xr = (const float4*)x + (size_t)(blockIdx.x * TB + xl) * Tn;

    // prologue: stager computes xp(0) into buf 0 (weights already visible)
    if (xw) stage_xp(sb, xr[0], xl, 0);

    const bool act = (tid < ACT);
    const bool varA = (tid < 128);      // warps 0-3 variant A; 4-6 variant B
    const int bg = tid / 50;
    const int u  = tid - bg * 50;
    const unsigned wq_off = (unsigned)u * 16;
    const unsigned hoff   = (unsigned)bg * 32;
    const unsigned hrow   = (unsigned)u * HSTR + hoff;
    const unsigned u512   = (unsigned)u * 512;

    u64 b1s[4];
    if (act) {
        float4 b1 = lds_f4(sb + O_BQ1 + wq_off);
        b1s[0] = pack2(b1.x); b1s[1] = pack2(b1.y); b1s[2] = pack2(b1.z); b1s[3] = pack2(b1.w);
    }

    float c0[8], c1[8];
    #pragma unroll
    for (int j = 0; j < 8; ++j) { c0[j] = 0.f; c1[j] = 0.f; }

    __syncthreads();    // xp(0) + zeroed h visible

    u64 acc0[4][4], acc1[4][4];

    // ---------- peel t = 0: l0 only; stager computes xp(1) -> buf 1 ----------
    {
        float4 xp4;
        if (xw) xp4 = xr[1];
        if (act) {
            gemv_l0(acc0, a_xp + 0, a_q0hh, a_h0 + 0, u512, wq_off, hoff);
            epilogue(acc0, c0, a_h0 + HBUFB + hrow);
        }
        if (xw) stage_xp(sb, xp4, xl, XPBUF);
        __syncthreads();
    }

    // ---------- fused intervals: l1(t-1) + l0(t), one sync each ----------
    for (int t = 1; t < Tn; ++t) {
        const unsigned hp = ((t - 1) & 1) ? HBUFB : 0u;   // p = (t-1)&1
        const unsigned hq = HBUFB - hp;                    // 1-p
        const unsigned xc = (t & 1) ? XPBUF : 0u;          // xp buffer for step t

        float4 xp4;
        if (xw && t + 1 < Tn) xp4 = xr[t + 1];

        if (act) {
            if (varA) {
                // A: l1g, l1e, l0g, l0e  (epi early)
                gemv_l1(acc1, b1s, a_q1ih, a_q1hh, a_h0 + hq, a_h1 + hp, wq_off, hoff);
                epilogue(acc1, c1, a_h1 + hq + hrow);
                gemv_l0(acc0, a_xp + xc, a_q0hh, a_h0 + hq, u512, wq_off, hoff);
                epilogue(acc0, c0, a_h0 + hp + hrow);
            } else {
                // B: l0g, l1g, l1e, l0e  (starts on a different LDS stream than A)
                gemv_l0(acc0, a_xp + xc, a_q0hh, a_h0 + hq, u512, wq_off, hoff);
                gemv_l1(acc1, b1s, a_q1ih, a_q1hh, a_h0 + hq, a_h1 + hp, wq_off, hoff);
                epilogue(acc1, c1, a_h1 + hq + hrow);
                epilogue(acc0, c0, a_h0 + hp + hrow);
            }
        }
        if (xw && t + 1 < Tn)
            stage_xp(sb, xp4, xl, XPBUF - xc);   // xp(t+1) -> buffer (t+1)&1
        __syncthreads();   // single sync per interval (hazards proven above)
    }

    // ---------- final l1(T-1): p = 1 -> reads h1[HBUFB], h0[0]; writes h1[0] ----------
    if (act) {
        gemv_l1(acc1, b1s, a_q1ih, a_q1hh, a_h0 + 0, a_h1 + HBUFB, wq_off, hoff);
        epilogue(acc1, c1, a_h1 + 0 + hrow);
    }
    __syncthreads();

    // ---- final FC: out = fcW @ h1_final + fcb (h1 in buffer 0) ----
    if (tid < TB * Fdim) {
        int b2 = tid >> 2, f = tid & 3;
        float a = fcb[f];
        const float* h1 = sm + (O_H1 / 4);
        #pragma unroll
        for (int j = 0; j < Hn; ++j)
            a = fmaf(fcW[f * Hn + j], h1[j * (HSTR / 4) + b2], a);
        out[((size_t)blockIdx.x * TB + b2) * Fdim + f] = a;
    }
}

extern "C" void kernel_launch(void* const* d_in, const int* in_sizes, int n_in,
                              void* d_out, int out_size) {
    const float* x    = (const float*)d_in[0];
    const float* Wih0 = (const float*)d_in[1];
    const float* Whh0 = (const float*)d_in[2];
    const float* bih0 = (const float*)d_in[3];
    const float* bhh0 = (const float*)d_in[4];
    const float* Wih1 = (const float*)d_in[5];
    const float* Whh1 = (const float*)d_in[6];
    const float* bih1 = (const float*)d_in[7];
    const float* bhh1 = (const float*)d_in[8];
    const float* fcW  = (const float*)d_in[9];
    const float* fcb  = (const float*)d_in[10];
    float* out = (float*)d_out;

    cudaFuncSetAttribute(lstm2_kernel,
                         cudaFuncAttributeMaxDynamicSharedMemorySize, SMEM_BYTES);
    lstm2_kernel<<<Bsz / TB, NT, SMEM_BYTES>>>(
        x, Wih0, Whh0, bih0, bhh0, Wih1, Whh1, bih1, bhh1, fcW, fcb, out);
}

// round 14
// speedup vs baseline: 1.0682x; 1.0682x over previous
#include <cuda_runtime.h>

#define Bsz   4096
#define Tn    512
#define Fdim  4
#define Hn    50
#define TB    32
#define NT    256
#define ACT   200     // active threads: u(50) x bg(4); thread owns 1 unit x 8 batches

// shared byte offsets (16B aligned)
#define O_Q0HH 0                    // [k][u][4g] quads: 50*50*16 = 40000
#define O_Q1IH 40000
#define O_Q1HH 80000
#define O_Q0IH 120000               // [kf][u][4g]: 3200
#define O_BQ0  123200               // [u][4g]: 800
#define O_BQ1  124000               // 800
#define O_H0   124800               // 2 bufs x 50*144 = 14400
#define O_H1   139200               // 14400
#define O_XB   153600               // 2 bufs x [4kf][32b] = 1024
#define SMEM_BYTES 154624
#define HSTR   144                  // bytes per k-row (32 batches*4B + 16 pad)
#define HBUFB  7200                 // one h buffer

using u64 = unsigned long long;

__device__ __forceinline__ u64 pack2(float v) {
    u64 r; unsigned i = __float_as_uint(v);
    asm("mov.b64 %0, {%1, %1};" : "=l"(r) : "r"(i));
    return r;
}
__device__ __forceinline__ u64 pack2two(float a, float b) {
    u64 r;
    asm("mov.b64 %0, {%1, %2};" : "=l"(r) : "r"(__float_as_uint(a)), "r"(__float_as_uint(b)));
    return r;
}
__device__ __forceinline__ void unpack2(u64 v, float& a, float& b) {
    unsigned lo, hi;
    asm("mov.b64 {%0, %1}, %2;" : "=r"(lo), "=r"(hi) : "l"(v));
    a = __uint_as_float(lo); b = __uint_as_float(hi);
}
__device__ __forceinline__ void ffma2(u64& d, u64 a, u64 b) {
    asm("fma.rn.f32x2 %0, %1, %2, %0;" : "+l"(d) : "l"(a), "l"(b));
}
__device__ __forceinline__ float4 lds_f4(unsigned addr) {
    float4 v;
    asm("ld.shared.v4.f32 {%0, %1, %2, %3}, [%4];"
        : "=f"(v.x), "=f"(v.y), "=f"(v.z), "=f"(v.w) : "r"(addr));
    return v;
}
__device__ __forceinline__ void lds_v2b64(u64& a, u64& b, unsigned addr) {
    asm("ld.shared.v2.b64 {%0, %1}, [%2];" : "=l"(a), "=l"(b) : "r"(addr));
}
__device__ __forceinline__ void sts_u64(unsigned addr, u64 v) {
    asm("st.shared.b64 [%0], %1;" :: "r"(addr), "l"(v));
}
__device__ __forceinline__ void sts_f32(unsigned addr, float v) {
    asm("st.shared.b32 [%0], %1;" :: "r"(addr), "f"(v));
}

// MUFU.TANH-based activations (1 MUFU each)
__device__ __forceinline__ float tanha(float x) {
    float r; asm("tanh.approx.f32 %0, %1;" : "=f"(r) : "f"(x));
    return r;
}
__device__ __forceinline__ float sigt(float x) {
    return fmaf(0.5f, tanha(0.5f * x), 0.5f);   // sigmoid via tanh identity
}

#define FMA16(A, W0, W1, W2, W3, V0, V1, V2, V3) do { \
    ffma2(A[0][0], W0, V0); ffma2(A[0][1], W0, V1); \
    ffma2(A[0][2], W0, V2); ffma2(A[0][3], W0, V3); \
    ffma2(A[1][0], W1, V0); ffma2(A[1][1], W1, V1); \
    ffma2(A[1][2], W1, V2); ffma2(A[1][3], W1, V3); \
    ffma2(A[2][0], W2, V0); ffma2(A[2][1], W2, V1); \
    ffma2(A[2][2], W2, V2); ffma2(A[2][3], W2, V3); \
    ffma2(A[3][0], W3, V0); ffma2(A[3][1], W3, V1); \
    ffma2(A[3][2], W3, V2); ffma2(A[3][3], W3, V3); \
} while (0)

// gates -> c (regs), h batch-pairs -> smem at dst
__device__ __forceinline__ void epilogue(u64 acc[4][4], float* c, unsigned dst) {
    #pragma unroll
    for (int bp = 0; bp < 4; ++bp) {
        float giA, giB, gfA, gfB, ggA, ggB, goA, goB;
        unpack2(acc[0][bp], giA, giB);
        unpack2(acc[1][bp], gfA, gfB);
        unpack2(acc[2][bp], ggA, ggB);
        unpack2(acc[3][bp], goA, goB);
        float cA = fmaf(sigt(gfA), c[2 * bp],     sigt(giA) * tanha(ggA));
        float cB = fmaf(sigt(gfB), c[2 * bp + 1], sigt(giB) * tanha(ggB));
        c[2 * bp] = cA; c[2 * bp + 1] = cB;
        sts_u64(dst + bp * 8,
                pack2two(sigt(goA) * tanha(cA), sigt(goB) * tanha(cB)));
    }
}

// layer 0 GEMV (standalone, for peel t=0): acc = bias + Wih0*x + Whh0*h0_prev
__device__ __forceinline__ void gemv_l0(u64 acc[4][4], const u64* bs,
                                        unsigned a_q0ih, unsigned a_q0hh,
                                        unsigned a_x, unsigned a_h,
                                        unsigned wq_off, unsigned hoff)
{
    #pragma unroll
    for (int g = 0; g < 4; ++g)
        #pragma unroll
        for (int bp = 0; bp < 4; ++bp) acc[g][bp] = bs[g];
    #pragma unroll
    for (int kf = 0; kf < Fdim; ++kf) {
        float4 w = lds_f4(a_q0ih + kf * 800 + wq_off);
        u64 x01, x23, x45, x67;
        lds_v2b64(x01, x23, a_x + kf * 128 + hoff);
        lds_v2b64(x45, x67, a_x + kf * 128 + hoff + 16);
        u64 w0 = pack2(w.x), w1 = pack2(w.y), w2 = pack2(w.z), w3 = pack2(w.w);
        FMA16(acc, w0, w1, w2, w3, x01, x23, x45, x67);
    }
    #pragma unroll 10
    for (int k = 0; k < Hn; ++k) {
        float4 w = lds_f4(a_q0hh + k * 800 + wq_off);
        u64 h01, h23, h45, h67;
        lds_v2b64(h01, h23, a_h + k * HSTR + hoff);
        lds_v2b64(h45, h67, a_h + k * HSTR + hoff + 16);
        u64 w0 = pack2(w.x), w1 = pack2(w.y), w2 = pack2(w.z), w3 = pack2(w.w);
        FMA16(acc, w0, w1, w2, w3, h01, h23, h45, h67);
    }
}

// layer 1 GEMV (standalone, for final step): acc = bias + Wih1*h0_new + Whh1*h1_prev
__device__ __forceinline__ void gemv_l1(u64 acc[4][4], const u64* bs,
                                        unsigned a_q1ih, unsigned a_q1hh,
                                        unsigned a_h0n, unsigned a_h1p,
                                        unsigned wq_off, unsigned hoff)
{
    #pragma unroll
    for (int g = 0; g < 4; ++g)
        #pragma unroll
        for (int bp = 0; bp < 4; ++bp) acc[g][bp] = bs[g];
    #pragma unroll 10
    for (int k = 0; k < Hn; ++k) {
        float4 wa = lds_f4(a_q1ih + k * 800 + wq_off);
        float4 wb = lds_f4(a_q1hh + k * 800 + wq_off);
        u64 p01, p23, p45, p67;
        lds_v2b64(p01, p23, a_h0n + k * HSTR + hoff);
        lds_v2b64(p45, p67, a_h0n + k * HSTR + hoff + 16);
        u64 q01, q23, q45, q67;
        lds_v2b64(q01, q23, a_h1p + k * HSTR + hoff);
        lds_v2b64(q45, q67, a_h1p + k * HSTR + hoff + 16);
        u64 a0 = pack2(wa.x), a1 = pack2(wa.y), a2 = pack2(wa.z), a3 = pack2(wa.w);
        u64 b0 = pack2(wb.x), b1 = pack2(wb.y), b2 = pack2(wb.z), b3 = pack2(wb.w);
        FMA16(acc, a0, a1, a2, a3, p01, p23, p45, p67);
        FMA16(acc, b0, b1, b2, b3, q01, q23, q45, q67);
    }
}

// FUSED interval GEMV: l1(t-1) and l0(t) share the h0[hq] row loads.
// acc0 = b0 + Wih0*x(t) + Whh0*h0(t-1);  acc1 = b1 + Wih1*h0(t-1) + Whh1*h1(t-1).
// Per-accumulator FMA order identical to the standalone gemvs (bit-identical results).
__device__ __forceinline__ void gemv_fused(u64 acc0[4][4], u64 acc1[4][4],
                                           const u64* b0s, const u64* b1s,
                                           unsigned a_q0ih, unsigned a_q0hh,
                                           unsigned a_q1ih, unsigned a_q1hh,
                                           unsigned a_x, unsigned a_h0q, unsigned a_h1p,
                                           unsigned wq_off, unsigned hoff)
{
    #pragma unroll
    for (int g = 0; g < 4; ++g)
        #pragma unroll
        for (int bp = 0; bp < 4; ++bp) { acc0[g][bp] = b0s[g]; acc1[g][bp] = b1s[g]; }
    #pragma unroll
    for (int kf = 0; kf < Fdim; ++kf) {
        float4 w = lds_f4(a_q0ih + kf * 800 + wq_off);
        u64 x01, x23, x45, x67;
        lds_v2b64(x01, x23, a_x + kf * 128 + hoff);
        lds_v2b64(x45, x67, a_x + kf * 128 + hoff + 16);
        u64 w0 = pack2(w.x), w1 = pack2(w.y), w2 = pack2(w.z), w3 = pack2(w.w);
        FMA16(acc0, w0, w1, w2, w3, x01, x23, x45, x67);
    }
    #pragma unroll 5
    for (int k = 0; k < Hn; ++k) {
        float4 w  = lds_f4(a_q0hh + k * 800 + wq_off);
        float4 wa = lds_f4(a_q1ih + k * 800 + wq_off);
        float4 wb = lds_f4(a_q1hh + k * 800 + wq_off);
        u64 p01, p23, p45, p67;                     // h0(t-1) pairs — SHARED
        lds_v2b64(p01, p23, a_h0q + k * HSTR + hoff);
        lds_v2b64(p45, p67, a_h0q + k * HSTR + hoff + 16);
        u64 q01, q23, q45, q67;                     // h1(t-1) pairs
        lds_v2b64(q01, q23, a_h1p + k * HSTR + hoff);
        lds_v2b64(q45, q67, a_h1p + k * HSTR + hoff + 16);
        u64 w0 = pack2(w.x),  w1 = pack2(w.y),  w2 = pack2(w.z),  w3 = pack2(w.w);
        u64 a0 = pack2(wa.x), a1 = pack2(wa.y), a2 = pack2(wa.z), a3 = pack2(wa.w);
        u64 b0 = pack2(wb.x), b1 = pack2(wb.y), b2 = pack2(wb.z), b3 = pack2(wb.w);
        FMA16(acc0, w0, w1, w2, w3, p01, p23, p45, p67);
        FMA16(acc1, a0, a1, a2, a3, p01, p23, p45, p67);
        FMA16(acc1, b0, b1, b2, b3, q01, q23, q45, q67);
    }
}

__global__ void __launch_bounds__(NT, 1) lstm2_kernel(
    const float* __restrict__ x,
    const float* __restrict__ Wih0, const float* __restrict__ Whh0,
    const float* __restrict__ bih0, const float* __restrict__ bhh0,
    const float* __restrict__ Wih1, const float* __restrict__ Whh1,
    const float* __restrict__ bih1, const float* __restrict__ bhh1,
    const float* __restrict__ fcW,  const float* __restrict__ fcb,
    float* __restrict__ out)
{
    extern __shared__ float sm[];
    const int tid = threadIdx.x;

    // ---- stage weights as per-unit gate quads [wi,wf,wg,wo] ----
    for (int i = tid; i < Hn * Hn; i += NT) {          // i = k*50 + u
        int k = i / Hn, u = i - k * Hn;
        float* q0 = sm + (O_Q0HH / 4) + i * 4;
        q0[0] = Whh0[(      u) * Hn + k];
        q0[1] = Whh0[( 50 + u) * Hn + k];
        q0[2] = Whh0[(100 + u) * Hn + k];
        q0[3] = Whh0[(150 + u) * Hn + k];
        float* q1i = sm + (O_Q1IH / 4) + i * 4;
        q1i[0] = Wih1[(      u) * Hn + k];
        q1i[1] = Wih1[( 50 + u) * Hn + k];
        q1i[2] = Wih1[(100 + u) * Hn + k];
        q1i[3] = Wih1[(150 + u) * Hn + k];
        float* q1h = sm + (O_Q1HH / 4) + i * 4;
        q1h[0] = Whh1[(      u) * Hn + k];
        q1h[1] = Whh1[( 50 + u) * Hn + k];
        q1h[2] = Whh1[(100 + u) * Hn + k];
        q1h[3] = Whh1[(150 + u) * Hn + k];
    }
    for (int i = tid; i < Fdim * Hn; i += NT) {        // i = kf*50 + u
        int kf = i / Hn, u = i - kf * Hn;
        float* q = sm + (O_Q0IH / 4) + i * 4;
        q[0] = Wih0[(      u) * Fdim + kf];
        q[1] = Wih0[( 50 + u) * Fdim + kf];
        q[2] = Wih0[(100 + u) * Fdim + kf];
        q[3] = Wih0[(150 + u) * Fdim + kf];
    }
    for (int u = tid; u < Hn; u += NT) {
        float* b0 = sm + (O_BQ0 / 4) + u * 4;
        b0[0] = bih0[u]       + bhh0[u];
        b0[1] = bih0[50 + u]  + bhh0[50 + u];
        b0[2] = bih0[100 + u] + bhh0[100 + u];
        b0[3] = bih0[150 + u] + bhh0[150 + u];
        float* b1 = sm + (O_BQ1 / 4) + u * 4;
        b1[0] = bih1[u]       + bhh1[u];
        b1[1] = bih1[50 + u]  + bhh1[50 + u];
        b1[2] = bih1[100 + u] + bhh1[100 + u];
        b1[3] = bih1[150 + u] + bhh1[150 + u];
    }
    for (int i = tid; i < (2 * HBUFB * 2 + 1024) / 4; i += NT)   // zero h bufs + x bufs
        sm[(O_H0 / 4) + i] = 0.f;
    __syncthreads();

    const unsigned sb = (unsigned)__cvta_generic_to_shared(sm);
    const unsigned a_q0ih = sb + O_Q0IH;
    const unsigned a_q0hh = sb + O_Q0HH;
    const unsigned a_q1ih = sb + O_Q1IH;
    const unsigned a_q1hh = sb + O_Q1HH;
    const unsigned a_h0   = sb + O_H0;
    const unsigned a_h1   = sb + O_H1;
    const unsigned a_xb   = sb + O_XB;

    // x staging handled by warp 7 (tid 224-255, no compute slots)
    const bool xw = (tid >= 224);
    const int  xl = tid & 31;
    const float4* xr = (const float4*)x + (size_t)(blockIdx.x * TB + xl) * Tn;

    // stage x[0] into xbuf[0]
    if (xw) {
        float4 v = xr[0];
        sts_f32(a_xb + 0 * 128 + xl * 4, v.x);
        sts_f32(a_xb + 1 * 128 + xl * 4, v.y);
        sts_f32(a_xb + 2 * 128 + xl * 4, v.z);
        sts_f32(a_xb + 3 * 128 + xl * 4, v.w);
    }

    const bool act = (tid < ACT);
    const bool varA = (tid < 128);      // warps 0-3 variant A; 4-6 variant B
    const int bg = tid / 50;
    const int u  = tid - bg * 50;
    const unsigned wq_off = (unsigned)u * 16;
    const unsigned hoff   = (unsigned)bg * 32;
    const unsigned hrow   = (unsigned)u * HSTR + hoff;

    u64 b0s[4], b1s[4];
    if (act) {
        float4 b0 = lds_f4(sb + O_BQ0 + wq_off);
        float4 b1 = lds_f4(sb + O_BQ1 + wq_off);
        b0s[0] = pack2(b0.x); b0s[1] = pack2(b0.y); b0s[2] = pack2(b0.z); b0s[3] = pack2(b0.w);
        b1s[0] = pack2(b1.x); b1s[1] = pack2(b1.y); b1s[2] = pack2(b1.z); b1s[3] = pack2(b1.w);
    }

    float c0[8], c1[8];
    #pragma unroll
    for (int j = 0; j < 8; ++j) { c0[j] = 0.f; c1[j] = 0.f; }

    __syncthreads();    // x[0] + weights + zeroed h visible

    u64 acc0[4][4], acc1[4][4];

    // ---------- peel t = 0: l0 only ----------
    {
        float4 xp4;
        if (xw) xp4 = xr[1];
        if (act) {
            gemv_l0(acc0, b0s, a_q0ih, a_q0hh, a_xb + 0, a_h0 + 0, wq_off, hoff);
            epilogue(acc0, c0, a_h0 + HBUFB + hrow);
        }
        if (xw) {
            sts_f32(a_xb + 512 + 0 * 128 + xl * 4, xp4.x);
            sts_f32(a_xb + 512 + 1 * 128 + xl * 4, xp4.y);
            sts_f32(a_xb + 512 + 2 * 128 + xl * 4, xp4.z);
            sts_f32(a_xb + 512 + 3 * 128 + xl * 4, xp4.w);
        }
        __syncthreads();
    }

    // ---------- fused intervals: l1(t-1) + l0(t) in ONE k-loop, one sync each ----------
    for (int t = 1; t < Tn; ++t) {
        const unsigned hp = ((t - 1) & 1) ? HBUFB : 0u;   // p = (t-1)&1
        const unsigned hq = HBUFB - hp;                    // 1-p
        const unsigned xc = (t & 1) ? 512u : 0u;

        float4 xp4;
        if (xw && t + 1 < Tn) xp4 = xr[t + 1];

        if (act) {
            gemv_fused(acc0, acc1, b0s, b1s,
                       a_q0ih, a_q0hh, a_q1ih, a_q1hh,
                       a_xb + xc, a_h0 + hq, a_h1 + hp, wq_off, hoff);
            if (varA) {
                epilogue(acc1, c1, a_h1 + hq + hrow);
                epilogue(acc0, c0, a_h0 + hp + hrow);
            } else {
                epilogue(acc0, c0, a_h0 + hp + hrow);
                epilogue(acc1, c1, a_h1 + hq + hrow);
            }
        }
        if (xw && t + 1 < Tn) {
            const unsigned xn = 512u - xc;
            sts_f32(a_xb + xn + 0 * 128 + xl * 4, xp4.x);
            sts_f32(a_xb + xn + 1 * 128 + xl * 4, xp4.y);
            sts_f32(a_xb + xn + 2 * 128 + xl * 4, xp4.z);
            sts_f32(a_xb + xn + 3 * 128 + xl * 4, xp4.w);
        }
        __syncthreads();   // single sync per interval (same hazard sets as R12)
    }

    // ---------- final l1(T-1): p = 1 -> reads h1[HBUFB], h0[0]; writes h1[0] ----------
    if (act) {
        gemv_l1(acc1, b1s, a_q1ih, a_q1hh, a_h0 + 0, a_h1 + HBUFB, wq_off, hoff);
        epilogue(acc1, c1, a_h1 + 0 + hrow);
    }
    __syncthreads();

    // ---- final FC: out = fcW @ h1_final + fcb (h1 in buffer 0) ----
    if (tid < TB * Fdim) {
        int b2 = tid >> 2, f = tid & 3;
        float a = fcb[f];
        const float* h1 = sm + (O_H1 / 4);
        #pragma unroll
        for (int j = 0; j < Hn; ++j)
            a = fmaf(fcW[f * Hn + j], h1[j * (HSTR / 4) + b2], a);
        out[((size_t)blockIdx.x * TB + b2) * Fdim + f] = a;
    }
}

extern "C" void kernel_launch(void* const* d_in, const int* in_sizes, int n_in,
                              void* d_out, int out_size) {
    const float* x    = (const float*)d_in[0];
    const float* Wih0 = (const float*)d_in[1];
    const float* Whh0 = (const float*)d_in[2];
    const float* bih0 = (const float*)d_in[3];
    const float* bhh0 = (const float*)d_in[4];
    const float* Wih1 = (const float*)d_in[5];
    const float* Whh1 = (const float*)d_in[6];
    const float* bih1 = (const float*)d_in[7];
    const float* bhh1 = (const float*)d_in[8];
    const float* fcW  = (const float*)d_in[9];
    const float* fcb  = (const float*)d_in[10];
    float* out = (float*)d_out;

    cudaFuncSetAttribute(lstm2_kernel,
                         cudaFuncAttributeMaxDynamicSharedMemorySize, SMEM_BYTES);
    lstm2_kernel<<<Bsz / TB, NT, SMEM_BYTES>>>(
        x, Wih0, Whh0, bih0, bhh0, Wih1, Whh1, bih1, bhh1, fcW, fcb, out);
}

// round 15
// speedup vs baseline: 1.1574x; 1.0835x over previous
#include <cuda_runtime.h>

#define Bsz   4096
#define Tn    512
#define Fdim  4
#define Hn    50
#define TB    32
#define NT    256
#define ACT   200     // active threads: u(50) x bg(4); thread owns 1 unit x 8 batches

// shared byte offsets (16B aligned)
#define O_Q0HH 0                    // [k][u][4g] quads: 50*50*16 = 40000
#define O_Q1IH 40000
#define O_Q1HH 80000
#define O_Q0IH 120000               // [kf][u][4g]: 3200
#define O_BQ0  123200               // [u][4g]: 800
#define O_BQ1  124000               // 800
#define O_H0   124800               // 2 bufs x 50*144 = 14400
#define O_H1   139200               // 14400
#define O_XB   153600               // 2 bufs x [4kf][32b] = 1024
#define SMEM_BYTES 154624
#define HSTR   144                  // bytes per k-row (32 batches*4B + 16 pad)
#define HBUFB  7200                 // one h buffer

using u64 = unsigned long long;

__device__ __forceinline__ u64 pack2(float v) {
    u64 r; unsigned i = __float_as_uint(v);
    asm("mov.b64 %0, {%1, %1};" : "=l"(r) : "r"(i));
    return r;
}
__device__ __forceinline__ u64 pack2two(float a, float b) {
    u64 r;
    asm("mov.b64 %0, {%1, %2};" : "=l"(r) : "r"(__float_as_uint(a)), "r"(__float_as_uint(b)));
    return r;
}
__device__ __forceinline__ void unpack2(u64 v, float& a, float& b) {
    unsigned lo, hi;
    asm("mov.b64 {%0, %1}, %2;" : "=r"(lo), "=r"(hi) : "l"(v));
    a = __uint_as_float(lo); b = __uint_as_float(hi);
}
__device__ __forceinline__ void ffma2(u64& d, u64 a, u64 b) {
    asm("fma.rn.f32x2 %0, %1, %2, %0;" : "+l"(d) : "l"(a), "l"(b));
}
__device__ __forceinline__ float4 lds_f4(unsigned addr) {
    float4 v;
    asm("ld.shared.v4.f32 {%0, %1, %2, %3}, [%4];"
        : "=f"(v.x), "=f"(v.y), "=f"(v.z), "=f"(v.w) : "r"(addr));
    return v;
}
__device__ __forceinline__ void lds_v2b64(u64& a, u64& b, unsigned addr) {
    asm("ld.shared.v2.b64 {%0, %1}, [%2];" : "=l"(a), "=l"(b) : "r"(addr));
}
__device__ __forceinline__ void sts_u64(unsigned addr, u64 v) {
    asm("st.shared.b64 [%0], %1;" :: "r"(addr), "l"(v));
}
__device__ __forceinline__ void sts_f32(unsigned addr, float v) {
    asm("st.shared.b32 [%0], %1;" :: "r"(addr), "f"(v));
}

// MUFU.TANH-based activations (1 MUFU each)
__device__ __forceinline__ float tanha(float x) {
    float r; asm("tanh.approx.f32 %0, %1;" : "=f"(r) : "f"(x));
    return r;
}
__device__ __forceinline__ float sigt(float x) {
    return fmaf(0.5f, tanha(0.5f * x), 0.5f);   // sigmoid via tanh identity
}

#define FMA16(A, W0, W1, W2, W3, V0, V1, V2, V3) do { \
    ffma2(A[0][0], W0, V0); ffma2(A[0][1], W0, V1); \
    ffma2(A[0][2], W0, V2); ffma2(A[0][3], W0, V3); \
    ffma2(A[1][0], W1, V0); ffma2(A[1][1], W1, V1); \
    ffma2(A[1][2], W1, V2); ffma2(A[1][3], W1, V3); \
    ffma2(A[2][0], W2, V0); ffma2(A[2][1], W2, V1); \
    ffma2(A[2][2], W2, V2); ffma2(A[2][3], W2, V3); \
    ffma2(A[3][0], W3, V0); ffma2(A[3][1], W3, V1); \
    ffma2(A[3][2], W3, V2); ffma2(A[3][3], W3, V3); \
} while (0)

// gates -> c (regs), h batch-pairs -> smem at dst
__device__ __forceinline__ void epilogue(u64 acc[4][4], float* c, unsigned dst) {
    #pragma unroll
    for (int bp = 0; bp < 4; ++bp) {
        float giA, giB, gfA, gfB, ggA, ggB, goA, goB;
        unpack2(acc[0][bp], giA, giB);
        unpack2(acc[1][bp], gfA, gfB);
        unpack2(acc[2][bp], ggA, ggB);
        unpack2(acc[3][bp], goA, goB);
        float cA = fmaf(sigt(gfA), c[2 * bp],     sigt(giA) * tanha(ggA));
        float cB = fmaf(sigt(gfB), c[2 * bp + 1], sigt(giB) * tanha(ggB));
        c[2 * bp] = cA; c[2 * bp + 1] = cB;
        sts_u64(dst + bp * 8,
                pack2two(sigt(goA) * tanha(cA), sigt(goB) * tanha(cB)));
    }
}

// layer 0 GEMV: acc = bias + Wih0*x + Whh0*h0_prev
__device__ __forceinline__ void gemv_l0(u64 acc[4][4], const u64* bs,
                                        unsigned a_q0ih, unsigned a_q0hh,
                                        unsigned a_x, unsigned a_h,
                                        unsigned wq_off, unsigned hoff)
{
    #pragma unroll
    for (int g = 0; g < 4; ++g)
        #pragma unroll
        for (int bp = 0; bp < 4; ++bp) acc[g][bp] = bs[g];
    #pragma unroll
    for (int kf = 0; kf < Fdim; ++kf) {
        float4 w = lds_f4(a_q0ih + kf * 800 + wq_off);
        u64 x01, x23, x45, x67;
        lds_v2b64(x01, x23, a_x + kf * 128 + hoff);
        lds_v2b64(x45, x67, a_x + kf * 128 + hoff + 16);
        u64 w0 = pack2(w.x), w1 = pack2(w.y), w2 = pack2(w.z), w3 = pack2(w.w);
        FMA16(acc, w0, w1, w2, w3, x01, x23, x45, x67);
    }
    #pragma unroll 10
    for (int k = 0; k < Hn; ++k) {
        float4 w = lds_f4(a_q0hh + k * 800 + wq_off);
        u64 h01, h23, h45, h67;
        lds_v2b64(h01, h23, a_h + k * HSTR + hoff);
        lds_v2b64(h45, h67, a_h + k * HSTR + hoff + 16);
        u64 w0 = pack2(w.x), w1 = pack2(w.y), w2 = pack2(w.z), w3 = pack2(w.w);
        FMA16(acc, w0, w1, w2, w3, h01, h23, h45, h67);
    }
}

// layer 1 GEMV: acc = bias + Wih1*h0_new + Whh1*h1_prev
__device__ __forceinline__ void gemv_l1(u64 acc[4][4], const u64* bs,
                                        unsigned a_q1ih, unsigned a_q1hh,
                                        unsigned a_h0n, unsigned a_h1p,
                                        unsigned wq_off, unsigned hoff)
{
    #pragma unroll
    for (int g = 0; g < 4; ++g)
        #pragma unroll
        for (int bp = 0; bp < 4; ++bp) acc[g][bp] = bs[g];
    #pragma unroll 10
    for (int k = 0; k < Hn; ++k) {
        float4 wa = lds_f4(a_q1ih + k * 800 + wq_off);
        float4 wb = lds_f4(a_q1hh + k * 800 + wq_off);
        u64 p01, p23, p45, p67;
        lds_v2b64(p01, p23, a_h0n + k * HSTR + hoff);
        lds_v2b64(p45, p67, a_h0n + k * HSTR + hoff + 16);
        u64 q01, q23, q45, q67;
        lds_v2b64(q01, q23, a_h1p + k * HSTR + hoff);
        lds_v2b64(q45, q67, a_h1p + k * HSTR + hoff + 16);
        u64 a0 = pack2(wa.x), a1 = pack2(wa.y), a2 = pack2(wa.z), a3 = pack2(wa.w);
        u64 b0 = pack2(wb.x), b1 = pack2(wb.y), b2 = pack2(wb.z), b3 = pack2(wb.w);
        FMA16(acc, a0, a1, a2, a3, p01, p23, p45, p67);
        FMA16(acc, b0, b1, b2, b3, q01, q23, q45, q67);
    }
}

__global__ void __launch_bounds__(NT, 1) lstm2_kernel(
    const float* __restrict__ x,
    const float* __restrict__ Wih0, const float* __restrict__ Whh0,
    const float* __restrict__ bih0, const float* __restrict__ bhh0,
    const float* __restrict__ Wih1, const float* __restrict__ Whh1,
    const float* __restrict__ bih1, const float* __restrict__ bhh1,
    const float* __restrict__ fcW,  const float* __restrict__ fcb,
    float* __restrict__ out)
{
    extern __shared__ float sm[];
    const int tid = threadIdx.x;

    // ---- stage weights as per-unit gate quads [wi,wf,wg,wo] ----
    for (int i = tid; i < Hn * Hn; i += NT) {          // i = k*50 + u
        int k = i / Hn, u = i - k * Hn;
        float* q0 = sm + (O_Q0HH / 4) + i * 4;
        q0[0] = Whh0[(      u) * Hn + k];
        q0[1] = Whh0[( 50 + u) * Hn + k];
        q0[2] = Whh0[(100 + u) * Hn + k];
        q0[3] = Whh0[(150 + u) * Hn + k];
        float* q1i = sm + (O_Q1IH / 4) + i * 4;
        q1i[0] = Wih1[(      u) * Hn + k];
        q1i[1] = Wih1[( 50 + u) * Hn + k];
        q1i[2] = Wih1[(100 + u) * Hn + k];
        q1i[3] = Wih1[(150 + u) * Hn + k];
        float* q1h = sm + (O_Q1HH / 4) + i * 4;
        q1h[0] = Whh1[(      u) * Hn + k];
        q1h[1] = Whh1[( 50 + u) * Hn + k];
        q1h[2] = Whh1[(100 + u) * Hn + k];
        q1h[3] = Whh1[(150 + u) * Hn + k];
    }
    for (int i = tid; i < Fdim * Hn; i += NT) {        // i = kf*50 + u
        int kf = i / Hn, u = i - kf * Hn;
        float* q = sm + (O_Q0IH / 4) + i * 4;
        q[0] = Wih0[(      u) * Fdim + kf];
        q[1] = Wih0[( 50 + u) * Fdim + kf];
        q[2] = Wih0[(100 + u) * Fdim + kf];
        q[3] = Wih0[(150 + u) * Fdim + kf];
    }
    for (int u = tid; u < Hn; u += NT) {
        float* b0 = sm + (O_BQ0 / 4) + u * 4;
        b0[0] = bih0[u]       + bhh0[u];
        b0[1] = bih0[50 + u]  + bhh0[50 + u];
        b0[2] = bih0[100 + u] + bhh0[100 + u];
        b0[3] = bih0[150 + u] + bhh0[150 + u];
        float* b1 = sm + (O_BQ1 / 4) + u * 4;
        b1[0] = bih1[u]       + bhh1[u];
        b1[1] = bih1[50 + u]  + bhh1[50 + u];
        b1[2] = bih1[100 + u] + bhh1[100 + u];
        b1[3] = bih1[150 + u] + bhh1[150 + u];
    }
    for (int i = tid; i < (2 * HBUFB * 2 + 1024) / 4; i += NT)   // zero h bufs + x bufs
        sm[(O_H0 / 4) + i] = 0.f;
    __syncthreads();

    const unsigned sb = (unsigned)__cvta_generic_to_shared(sm);
    const unsigned a_q0ih = sb + O_Q0IH;
    const unsigned a_q0hh = sb + O_Q0HH;
    const unsigned a_q1ih = sb + O_Q1IH;
    const unsigned a_q1hh = sb + O_Q1HH;
    const unsigned a_h0   = sb + O_H0;
    const unsigned a_h1   = sb + O_H1;
    const unsigned a_xb   = sb + O_XB;

    // x staging handled by warp 7 (tid 224-255, no compute slots)
    const bool xw = (tid >= 224);
    const int  xl = tid & 31;
    const float4* xr = (const float4*)x + (size_t)(blockIdx.x * TB + xl) * Tn;

    // stage x[0] into xbuf[0]
    if (xw) {
        float4 v = xr[0];
        sts_f32(a_xb + 0 * 128 + xl * 4, v.x);
        sts_f32(a_xb + 1 * 128 + xl * 4, v.y);
        sts_f32(a_xb + 2 * 128 + xl * 4, v.z);
        sts_f32(a_xb + 3 * 128 + xl * 4, v.w);
    }

    const bool act = (tid < ACT);
    const bool varA = (tid < 128);      // warps 0-3 variant A; 4-6 variant B
    const int bg = tid / 50;
    const int u  = tid - bg * 50;
    const unsigned wq_off = (unsigned)u * 16;
    const unsigned hoff   = (unsigned)bg * 32;
    const unsigned hrow   = (unsigned)u * HSTR + hoff;

    u64 b0s[4], b1s[4];
    if (act) {
        float4 b0 = lds_f4(sb + O_BQ0 + wq_off);
        float4 b1 = lds_f4(sb + O_BQ1 + wq_off);
        b0s[0] = pack2(b0.x); b0s[1] = pack2(b0.y); b0s[2] = pack2(b0.z); b0s[3] = pack2(b0.w);
        b1s[0] = pack2(b1.x); b1s[1] = pack2(b1.y); b1s[2] = pack2(b1.z); b1s[3] = pack2(b1.w);
    }

    float c0[8], c1[8];
    #pragma unroll
    for (int j = 0; j < 8; ++j) { c0[j] = 0.f; c1[j] = 0.f; }

    __syncthreads();    // x[0] + weights + zeroed h visible

    u64 acc0[4][4], acc1[4][4];

    // ---------- peel t = 0: l0 only ----------
    {
        float4 xp4;
        if (xw) xp4 = xr[1];
        if (act) {
            gemv_l0(acc0, b0s, a_q0ih, a_q0hh, a_xb + 0, a_h0 + 0, wq_off, hoff);
            epilogue(acc0, c0, a_h0 + HBUFB + hrow);
        }
        if (xw) {
            sts_f32(a_xb + 512 + 0 * 128 + xl * 4, xp4.x);
            sts_f32(a_xb + 512 + 1 * 128 + xl * 4, xp4.y);
            sts_f32(a_xb + 512 + 2 * 128 + xl * 4, xp4.z);
            sts_f32(a_xb + 512 + 3 * 128 + xl * 4, xp4.w);
        }
        __syncthreads();
    }

    // ---------- fused intervals: l1(t-1) + l0(t), one sync each ----------
    for (int t = 1; t < Tn; ++t) {
        const unsigned hp = ((t - 1) & 1) ? HBUFB : 0u;   // p = (t-1)&1
        const unsigned hq = HBUFB - hp;                    // 1-p
        const unsigned xc = (t & 1) ? 512u : 0u;

        float4 xp4;
        if (xw && t + 1 < Tn) xp4 = xr[t + 1];

        if (act) {
            if (varA) {
                // A: l1g, l1e, l0g, l0e  (epis at 55% and 100% of A's work)
                gemv_l1(acc1, b1s, a_q1ih, a_q1hh, a_h0 + hq, a_h1 + hp, wq_off, hoff);
                epilogue(acc1, c1, a_h1 + hq + hrow);
                gemv_l0(acc0, b0s, a_q0ih, a_q0hh, a_xb + xc, a_h0 + hq, wq_off, hoff);
                epilogue(acc0, c0, a_h0 + hp + hrow);
            } else {
                // B: l0g, l0e, l1g, l1e  (epis at 35% and 100%) — B's first epi
                // hides under A's long l1g; tail now has only 2 epis (A:l0e, B:l1e).
                // Legal: l0e writes h0[hp], read by nobody this interval (l1g reads h0[hq]).
                gemv_l0(acc0, b0s, a_q0ih, a_q0hh, a_xb + xc, a_h0 + hq, wq_off, hoff);
                epilogue(acc0, c0, a_h0 + hp + hrow);
                gemv_l1(acc1, b1s, a_q1ih, a_q1hh, a_h0 + hq, a_h1 + hp, wq_off, hoff);
                epilogue(acc1, c1, a_h1 + hq + hrow);
            }
        }
        if (xw && t + 1 < Tn) {
            const unsigned xn = 512u - xc;
            sts_f32(a_xb + xn + 0 * 128 + xl * 4, xp4.x);
            sts_f32(a_xb + xn + 1 * 128 + xl * 4, xp4.y);
            sts_f32(a_xb + xn + 2 * 128 + xl * 4, xp4.z);
            sts_f32(a_xb + xn + 3 * 128 + xl * 4, xp4.w);
        }
        __syncthreads();   // single sync per interval (hazards proven above)
    }

    // ---------- final l1(T-1): p = 1 -> reads h1[HBUFB], h0[0]; writes h1[0] ----------
    if (act) {
        gemv_l1(acc1, b1s, a_q1ih, a_q1hh, a_h0 + 0, a_h1 + HBUFB, wq_off, hoff);
        epilogue(acc1, c1, a_h1 + 0 + hrow);
    }
    __syncthreads();

    // ---- final FC: out = fcW @ h1_final + fcb (h1 in buffer 0) ----
    if (tid < TB * Fdim) {
        int b2 = tid >> 2, f = tid & 3;
        float a = fcb[f];
        const float* h1 = sm + (O_H1 / 4);
        #pragma unroll
        for (int j = 0; j < Hn; ++j)
            a = fmaf(fcW[f * Hn + j], h1[j * (HSTR / 4) + b2], a);
        out[((size_t)blockIdx.x * TB + b2) * Fdim + f] = a;
    }
}

extern "C" void kernel_launch(void* const* d_in, const int* in_sizes, int n_in,
                              void* d_out, int out_size) {
    const float* x    = (const float*)d_in[0];
    const float* Wih0 = (const float*)d_in[1];
    const float* Whh0 = (const float*)d_in[2];
    const float* bih0 = (const float*)d_in[3];
    const float* bhh0 = (const float*)d_in[4];
    const float* Wih1 = (const float*)d_in[5];
    const float* Whh1 = (const float*)d_in[6];
    const float* bih1 = (const float*)d_in[7];
    const float* bhh1 = (const float*)d_in[8];
    const float* fcW  = (const float*)d_in[9];
    const float* fcb  = (const float*)d_in[10];
    float* out = (float*)d_out;

    cudaFuncSetAttribute(lstm2_kernel,
                         cudaFuncAttributeMaxDynamicSharedMemorySize, SMEM_BYTES);
    lstm2_kernel<<<Bsz / TB, NT, SMEM_BYTES>>>(
        x, Wih0, Whh0, bih0, bhh0, Wih1, Whh1, bih1, bhh1, fcW, fcb, out);
}

// round 16
// speedup vs baseline: 1.1778x; 1.0176x over previous
#include <cuda_runtime.h>

#define Bsz   4096
#define Tn    512
#define Fdim  4
#define Hn    50
#define TB    32
#define NT    256

// shared byte offsets (16B aligned)
#define O_Q0HH 0                    // [k][u][4g] quads: 50*50*16 = 40000
#define O_Q1IH 40000
#define O_Q1HH 80000
#define O_Q0IH 120000               // [kf][u][4g]: 3200
#define O_BQ0  123200               // [u][4g]: 800
#define O_BQ1  124000               // 800
#define O_H0   124800               // 2 bufs x 50*144 = 14400
#define O_H1   139200               // 14400
#define O_XB   153600               // 2 bufs x [4kf][32b] = 1024
#define SMEM_BYTES 154624
#define HSTR   144                  // bytes per k-row (32 batches*4B + 16 pad)
#define HBUFB  7200                 // one h buffer

using u64 = unsigned long long;

__device__ __forceinline__ u64 pack2(float v) {
    u64 r; unsigned i = __float_as_uint(v);
    asm("mov.b64 %0, {%1, %1};" : "=l"(r) : "r"(i));
    return r;
}
__device__ __forceinline__ u64 pack2two(float a, float b) {
    u64 r;
    asm("mov.b64 %0, {%1, %2};" : "=l"(r) : "r"(__float_as_uint(a)), "r"(__float_as_uint(b)));
    return r;
}
__device__ __forceinline__ void unpack2(u64 v, float& a, float& b) {
    unsigned lo, hi;
    asm("mov.b64 {%0, %1}, %2;" : "=r"(lo), "=r"(hi) : "l"(v));
    a = __uint_as_float(lo); b = __uint_as_float(hi);
}
__device__ __forceinline__ void ffma2(u64& d, u64 a, u64 b) {
    asm("fma.rn.f32x2 %0, %1, %2, %0;" : "+l"(d) : "l"(a), "l"(b));
}
__device__ __forceinline__ float4 lds_f4(unsigned addr) {
    float4 v;
    asm("ld.shared.v4.f32 {%0, %1, %2, %3}, [%4];"
        : "=f"(v.x), "=f"(v.y), "=f"(v.z), "=f"(v.w) : "r"(addr));
    return v;
}
__device__ __forceinline__ void lds_v2b64(u64& a, u64& b, unsigned addr) {
    asm("ld.shared.v2.b64 {%0, %1}, [%2];" : "=l"(a), "=l"(b) : "r"(addr));
}
__device__ __forceinline__ u64 lds_u64(unsigned addr) {
    u64 v; asm("ld.shared.b64 %0, [%1];" : "=l"(v) : "r"(addr));
    return v;
}
__device__ __forceinline__ void sts_u64(unsigned addr, u64 v) {
    asm("st.shared.b64 [%0], %1;" :: "r"(addr), "l"(v));
}
__device__ __forceinline__ void sts_f32(unsigned addr, float v) {
    asm("st.shared.b32 [%0], %1;" :: "r"(addr), "f"(v));
}

// MUFU.TANH-based activations (1 MUFU each)
__device__ __forceinline__ float tanha(float x) {
    float r; asm("tanh.approx.f32 %0, %1;" : "=f"(r) : "f"(x));
    return r;
}
__device__ __forceinline__ float sigt(float x) {
    return fmaf(0.5f, tanha(0.5f * x), 0.5f);   // sigmoid via tanh identity
}

#define FMA16(A, W0, W1, W2, W3, V0, V1, V2, V3) do { \
    ffma2(A[0][0], W0, V0); ffma2(A[0][1], W0, V1); \
    ffma2(A[0][2], W0, V2); ffma2(A[0][3], W0, V3); \
    ffma2(A[1][0], W1, V0); ffma2(A[1][1], W1, V1); \
    ffma2(A[1][2], W1, V2); ffma2(A[1][3], W1, V3); \
    ffma2(A[2][0], W2, V0); ffma2(A[2][1], W2, V1); \
    ffma2(A[2][2], W2, V2); ffma2(A[2][3], W2, V3); \
    ffma2(A[3][0], W3, V0); ffma2(A[3][1], W3, V1); \
    ffma2(A[3][2], W3, V2); ffma2(A[3][3], W3, V3); \
} while (0)

#define FMA12(A, W0, W1, W2, W3, V0, V1, V2) do { \
    ffma2(A[0][0], W0, V0); ffma2(A[0][1], W0, V1); ffma2(A[0][2], W0, V2); \
    ffma2(A[1][0], W1, V0); ffma2(A[1][1], W1, V1); ffma2(A[1][2], W1, V2); \
    ffma2(A[2][0], W2, V0); ffma2(A[2][1], W2, V1); ffma2(A[2][2], W2, V2); \
    ffma2(A[3][0], W3, V0); ffma2(A[3][1], W3, V1); ffma2(A[3][2], W3, V2); \
} while (0)

// ======================== 4-bp thread path (R15 verbatim) ========================

__device__ __forceinline__ void epilogue(u64 acc[4][4], float* c, unsigned dst) {
    #pragma unroll
    for (int bp = 0; bp < 4; ++bp) {
        float giA, giB, gfA, gfB, ggA, ggB, goA, goB;
        unpack2(acc[0][bp], giA, giB);
        unpack2(acc[1][bp], gfA, gfB);
        unpack2(acc[2][bp], ggA, ggB);
        unpack2(acc[3][bp], goA, goB);
        float cA = fmaf(sigt(gfA), c[2 * bp],     sigt(giA) * tanha(ggA));
        float cB = fmaf(sigt(gfB), c[2 * bp + 1], sigt(giB) * tanha(ggB));
        c[2 * bp] = cA; c[2 * bp + 1] = cB;
        sts_u64(dst + bp * 8,
                pack2two(sigt(goA) * tanha(cA), sigt(goB) * tanha(cB)));
    }
}

__device__ __forceinline__ void gemv_l0(u64 acc[4][4], const u64* bs,
                                        unsigned a_q0ih, unsigned a_q0hh,
                                        unsigned a_x, unsigned a_h,
                                        unsigned wq_off, unsigned hoff)
{
    #pragma unroll
    for (int g = 0; g < 4; ++g)
        #pragma unroll
        for (int bp = 0; bp < 4; ++bp) acc[g][bp] = bs[g];
    #pragma unroll
    for (int kf = 0; kf < Fdim; ++kf) {
        float4 w = lds_f4(a_q0ih + kf * 800 + wq_off);
        u64 x01, x23, x45, x67;
        lds_v2b64(x01, x23, a_x + kf * 128 + hoff);
        lds_v2b64(x45, x67, a_x + kf * 128 + hoff + 16);
        u64 w0 = pack2(w.x), w1 = pack2(w.y), w2 = pack2(w.z), w3 = pack2(w.w);
        FMA16(acc, w0, w1, w2, w3, x01, x23, x45, x67);
    }
    #pragma unroll 10
    for (int k = 0; k < Hn; ++k) {
        float4 w = lds_f4(a_q0hh + k * 800 + wq_off);
        u64 h01, h23, h45, h67;
        lds_v2b64(h01, h23, a_h + k * HSTR + hoff);
        lds_v2b64(h45, h67, a_h + k * HSTR + hoff + 16);
        u64 w0 = pack2(w.x), w1 = pack2(w.y), w2 = pack2(w.z), w3 = pack2(w.w);
        FMA16(acc, w0, w1, w2, w3, h01, h23, h45, h67);
    }
}

__device__ __forceinline__ void gemv_l1(u64 acc[4][4], const u64* bs,
                                        unsigned a_q1ih, unsigned a_q1hh,
                                        unsigned a_h0n, unsigned a_h1p,
                                        unsigned wq_off, unsigned hoff)
{
    #pragma unroll
    for (int g = 0; g < 4; ++g)
        #pragma unroll
        for (int bp = 0; bp < 4; ++bp) acc[g][bp] = bs[g];
    #pragma unroll 10
    for (int k = 0; k < Hn; ++k) {
        float4 wa = lds_f4(a_q1ih + k * 800 + wq_off);
        float4 wb = lds_f4(a_q1hh + k * 800 + wq_off);
        u64 p01, p23, p45, p67;
        lds_v2b64(p01, p23, a_h0n + k * HSTR + hoff);
        lds_v2b64(p45, p67, a_h0n + k * HSTR + hoff + 16);
        u64 q01, q23, q45, q67;
        lds_v2b64(q01, q23, a_h1p + k * HSTR + hoff);
        lds_v2b64(q45, q67, a_h1p + k * HSTR + hoff + 16);
        u64 a0 = pack2(wa.x), a1 = pack2(wa.y), a2 = pack2(wa.z), a3 = pack2(wa.w);
        u64 b0 = pack2(wb.x), b1 = pack2(wb.y), b2 = pack2(wb.z), b3 = pack2(wb.w);
        FMA16(acc, a0, a1, a2, a3, p01, p23, p45, p67);
        FMA16(acc, b0, b1, b2, b3, q01, q23, q45, q67);
    }
}

// ======================== 3-bp thread path (lean streams) ========================
// Thread owns 3 consecutive batch-pairs of one unit; full k -> complete gate sums.
// Same per-gate accumulation order as the 4-bp path (bit-identical results).

__device__ __forceinline__ void epilogue3(u64 acc[4][3], float* c, unsigned dst) {
    #pragma unroll
    for (int i = 0; i < 3; ++i) {
        float giA, giB, gfA, gfB, ggA, ggB, goA, goB;
        unpack2(acc[0][i], giA, giB);
        unpack2(acc[1][i], gfA, gfB);
        unpack2(acc[2][i], ggA, ggB);
        unpack2(acc[3][i], goA, goB);
        float cA = fmaf(sigt(gfA), c[2 * i],     sigt(giA) * tanha(ggA));
        float cB = fmaf(sigt(gfB), c[2 * i + 1], sigt(giB) * tanha(ggB));
        c[2 * i] = cA; c[2 * i + 1] = cB;
        sts_u64(dst + i * 8,
                pack2two(sigt(goA) * tanha(cA), sigt(goB) * tanha(cB)));
    }
}

__device__ __forceinline__ void gemv3_l0(u64 acc[4][3], const u64* bs,
                                         unsigned a_q0ih, unsigned a_q0hh,
                                         unsigned a_x, unsigned a_h,
                                         unsigned wq_off, unsigned hb)
{
    #pragma unroll
    for (int g = 0; g < 4; ++g)
        #pragma unroll
        for (int i = 0; i < 3; ++i) acc[g][i] = bs[g];
    #pragma unroll
    for (int kf = 0; kf < Fdim; ++kf) {
        float4 w = lds_f4(a_q0ih + kf * 800 + wq_off);
        u64 x0 = lds_u64(a_x + kf * 128 + hb);
        u64 x1 = lds_u64(a_x + kf * 128 + hb + 8);
        u64 x2 = lds_u64(a_x + kf * 128 + hb + 16);
        u64 w0 = pack2(w.x), w1 = pack2(w.y), w2 = pack2(w.z), w3 = pack2(w.w);
        FMA12(acc, w0, w1, w2, w3, x0, x1, x2);
    }
    #pragma unroll 10
    for (int k = 0; k < Hn; ++k) {
        float4 w = lds_f4(a_q0hh + k * 800 + wq_off);
        u64 h0 = lds_u64(a_h + k * HSTR + hb);
        u64 h1 = lds_u64(a_h + k * HSTR + hb + 8);
        u64 h2 = lds_u64(a_h + k * HSTR + hb + 16);
        u64 w0 = pack2(w.x), w1 = pack2(w.y), w2 = pack2(w.z), w3 = pack2(w.w);
        FMA12(acc, w0, w1, w2, w3, h0, h1, h2);
    }
}

__device__ __forceinline__ void gemv3_l1(u64 acc[4][3], const u64* bs,
                                         unsigned a_q1ih, unsigned a_q1hh,
                                         unsigned a_h0n, unsigned a_h1p,
                                         unsigned wq_off, unsigned hb)
{
    #pragma unroll
    for (int g = 0; g < 4; ++g)
        #pragma unroll
        for (int i = 0; i < 3; ++i) acc[g][i] = bs[g];
    #pragma unroll 10
    for (int k = 0; k < Hn; ++k) {
        float4 wa = lds_f4(a_q1ih + k * 800 + wq_off);
        float4 wb = lds_f4(a_q1hh + k * 800 + wq_off);
        u64 p0 = lds_u64(a_h0n + k * HSTR + hb);
        u64 p1 = lds_u64(a_h0n + k * HSTR + hb + 8);
        u64 p2 = lds_u64(a_h0n + k * HSTR + hb + 16);
        u64 q0 = lds_u64(a_h1p + k * HSTR + hb);
        u64 q1 = lds_u64(a_h1p + k * HSTR + hb + 8);
        u64 q2 = lds_u64(a_h1p + k * HSTR + hb + 16);
        u64 a0 = pack2(wa.x), a1 = pack2(wa.y), a2 = pack2(wa.z), a3 = pack2(wa.w);
        u64 b0 = pack2(wb.x), b1 = pack2(wb.y), b2 = pack2(wb.z), b3 = pack2(wb.w);
        FMA12(acc, a0, a1, a2, a3, p0, p1, p2);
        FMA12(acc, b0, b1, b2, b3, q0, q1, q2);
    }
}

__global__ void __launch_bounds__(NT, 1) lstm2_kernel(
    const float* __restrict__ x,
    const float* __restrict__ Wih0, const float* __restrict__ Whh0,
    const float* __restrict__ bih0, const float* __restrict__ bhh0,
    const float* __restrict__ Wih1, const float* __restrict__ Whh1,
    const float* __restrict__ bih1, const float* __restrict__ bhh1,
    const float* __restrict__ fcW,  const float* __restrict__ fcb,
    float* __restrict__ out)
{
    extern __shared__ float sm[];
    const int tid = threadIdx.x;

    // ---- stage weights as per-unit gate quads [wi,wf,wg,wo] ----
    for (int i = tid; i < Hn * Hn; i += NT) {          // i = k*50 + u
        int k = i / Hn, u = i - k * Hn;
        float* q0 = sm + (O_Q0HH / 4) + i * 4;
        q0[0] = Whh0[(      u) * Hn + k];
        q0[1] = Whh0[( 50 + u) * Hn + k];
        q0[2] = Whh0[(100 + u) * Hn + k];
        q0[3] = Whh0[(150 + u) * Hn + k];
        float* q1i = sm + (O_Q1IH / 4) + i * 4;
        q1i[0] = Wih1[(      u) * Hn + k];
        q1i[1] = Wih1[( 50 + u) * Hn + k];
        q1i[2] = Wih1[(100 + u) * Hn + k];
        q1i[3] = Wih1[(150 + u) * Hn + k];
        float* q1h = sm + (O_Q1HH / 4) + i * 4;
        q1h[0] = Whh1[(      u) * Hn + k];
        q1h[1] = Whh1[( 50 + u) * Hn + k];
        q1h[2] = Whh1[(100 + u) * Hn + k];
        q1h[3] = Whh1[(150 + u) * Hn + k];
    }
    for (int i = tid; i < Fdim * Hn; i += NT) {        // i = kf*50 + u
        int kf = i / Hn, u = i - kf * Hn;
        float* q = sm + (O_Q0IH / 4) + i * 4;
        q[0] = Wih0[(      u) * Fdim + kf];
        q[1] = Wih0[( 50 + u) * Fdim + kf];
        q[2] = Wih0[(100 + u) * Fdim + kf];
        q[3] = Wih0[(150 + u) * Fdim + kf];
    }
    for (int u = tid; u < Hn; u += NT) {
        float* b0 = sm + (O_BQ0 / 4) + u * 4;
        b0[0] = bih0[u]       + bhh0[u];
        b0[1] = bih0[50 + u]  + bhh0[50 + u];
        b0[2] = bih0[100 + u] + bhh0[100 + u];
        b0[3] = bih0[150 + u] + bhh0[150 + u];
        float* b1 = sm + (O_BQ1 / 4) + u * 4;
        b1[0] = bih1[u]       + bhh1[u];
        b1[1] = bih1[50 + u]  + bhh1[50 + u];
        b1[2] = bih1[100 + u] + bhh1[100 + u];
        b1[3] = bih1[150 + u] + bhh1[150 + u];
    }
    for (int i = tid; i < (2 * HBUFB * 2 + 1024) / 4; i += NT)   // zero h bufs + x bufs
        sm[(O_H0 / 4) + i] = 0.f;
    __syncthreads();

    const unsigned sb = (unsigned)__cvta_generic_to_shared(sm);
    const unsigned a_q0ih = sb + O_Q0IH;
    const unsigned a_q0hh = sb + O_Q0HH;
    const unsigned a_q1ih = sb + O_Q1IH;
    const unsigned a_q1hh = sb + O_Q1HH;
    const unsigned a_h0   = sb + O_H0;
    const unsigned a_h1   = sb + O_H1;
    const unsigned a_xb   = sb + O_XB;

    const int wid = tid >> 5;

    // x staging handled by warp 7 (tid 224-255)
    const bool xw = (tid >= 224);
    const int  xl = tid & 31;
    const float4* xr = (const float4*)x + (size_t)(blockIdx.x * TB + xl) * Tn;

    // stage x[0] into xbuf[0]
    if (xw) {
        float4 v = xr[0];
        sts_f32(a_xb + 0 * 128 + xl * 4, v.x);
        sts_f32(a_xb + 1 * 128 + xl * 4, v.y);
        sts_f32(a_xb + 2 * 128 + xl * 4, v.z);
        sts_f32(a_xb + 3 * 128 + xl * 4, v.w);
    }

    // ---- micro-cell partition: 800 (unit, batch-pair) cells ----
    // tid <104:       4-bp thread, pure-4 unit:  u = tid>>2 (0..25), bg = tid&3
    // 104<=tid<128:   4-bp thread, split unit:   u = 26+(tid-104) (26..49), bg = 0
    // 128<=tid<224:   3-bp thread: u = 26+((tid-128)>>2), chunk j = (tid-128)&3,
    //                 covers bps 4+3j .. 6+3j  (bytes 32+24j .. 32+24j+23)
    const bool is4 = (tid < 128);
    int u, hboff;
    if (tid < 104)      { u = tid >> 2;              hboff = (tid & 3) * 32; }
    else if (tid < 128) { u = 26 + (tid - 104);      hboff = 0; }
    else                { int m = tid - 128; u = 26 + (m >> 2); hboff = 32 + 24 * (m & 3); }
    const unsigned wq_off = (unsigned)u * 16;
    const unsigned hoff   = (unsigned)hboff;
    const unsigned hrow   = (unsigned)u * HSTR + hoff;

    // phase variant per warp, opposite within each SMSP pair:
    // SMSP0: w0(A4)+w4(B3); SMSP1: w1(A4)+w5(B3); SMSP2: w2(B4)+w6(A3); SMSP3: w3(B4)+stager
    const bool varA = (wid < 2) || (wid == 6);

    u64 b0s[4], b1s[4];
    if (!xw) {
        float4 b0 = lds_f4(sb + O_BQ0 + wq_off);
        float4 b1 = lds_f4(sb + O_BQ1 + wq_off);
        b0s[0] = pack2(b0.x); b0s[1] = pack2(b0.y); b0s[2] = pack2(b0.z); b0s[3] = pack2(b0.w);
        b1s[0] = pack2(b1.x); b1s[1] = pack2(b1.y); b1s[2] = pack2(b1.z); b1s[3] = pack2(b1.w);
    }

    float c0[8], c1[8];
    #pragma unroll
    for (int j = 0; j < 8; ++j) { c0[j] = 0.f; c1[j] = 0.f; }

    __syncthreads();    // x[0] + weights + zeroed h visible

    u64 acc0[4][4], acc1[4][4];     // 4-bp path accumulators
    u64 acc3a[4][3], acc3b[4][3];   // 3-bp path accumulators

    // ---------- peel t = 0: l0 only ----------
    {
        float4 xp4;
        if (xw) xp4 = xr[1];
        if (is4) {
            gemv_l0(acc0, b0s, a_q0ih, a_q0hh, a_xb + 0, a_h0 + 0, wq_off, hoff);
            epilogue(acc0, c0, a_h0 + HBUFB + hrow);
        } else if (!xw) {
            gemv3_l0(acc3a, b0s, a_q0ih, a_q0hh, a_xb + 0, a_h0 + 0, wq_off, hoff);
            epilogue3(acc3a, c0, a_h0 + HBUFB + hrow);
        }
        if (xw) {
            sts_f32(a_xb + 512 + 0 * 128 + xl * 4, xp4.x);
            sts_f32(a_xb + 512 + 1 * 128 + xl * 4, xp4.y);
            sts_f32(a_xb + 512 + 2 * 128 + xl * 4, xp4.z);
            sts_f32(a_xb + 512 + 3 * 128 + xl * 4, xp4.w);
        }
        __syncthreads();
    }

    // ---------- fused intervals: l1(t-1) + l0(t), one sync each ----------
    for (int t = 1; t < Tn; ++t) {
        const unsigned hp = ((t - 1) & 1) ? HBUFB : 0u;   // p = (t-1)&1
        const unsigned hq = HBUFB - hp;                    // 1-p
        const unsigned xc = (t & 1) ? 512u : 0u;

        float4 xp4;
        if (xw && t + 1 < Tn) xp4 = xr[t + 1];

        if (is4) {
            if (varA) {
                gemv_l1(acc1, b1s, a_q1ih, a_q1hh, a_h0 + hq, a_h1 + hp, wq_off, hoff);
                epilogue(acc1, c1, a_h1 + hq + hrow);
                gemv_l0(acc0, b0s, a_q0ih, a_q0hh, a_xb + xc, a_h0 + hq, wq_off, hoff);
                epilogue(acc0, c0, a_h0 + hp + hrow);
            } else {
                gemv_l0(acc0, b0s, a_q0ih, a_q0hh, a_xb + xc, a_h0 + hq, wq_off, hoff);
                epilogue(acc0, c0, a_h0 + hp + hrow);
                gemv_l1(acc1, b1s, a_q1ih, a_q1hh, a_h0 + hq, a_h1 + hp, wq_off, hoff);
                epilogue(acc1, c1, a_h1 + hq + hrow);
            }
        } else if (!xw) {
            if (varA) {
                gemv3_l1(acc3b, b1s, a_q1ih, a_q1hh, a_h0 + hq, a_h1 + hp, wq_off, hoff);
                epilogue3(acc3b, c1, a_h1 + hq + hrow);
                gemv3_l0(acc3a, b0s, a_q0ih, a_q0hh, a_xb + xc, a_h0 + hq, wq_off, hoff);
                epilogue3(acc3a, c0, a_h0 + hp + hrow);
            } else {
                gemv3_l0(acc3a, b0s, a_q0ih, a_q0hh, a_xb + xc, a_h0 + hq, wq_off, hoff);
                epilogue3(acc3a, c0, a_h0 + hp + hrow);
                gemv3_l1(acc3b, b1s, a_q1ih, a_q1hh, a_h0 + hq, a_h1 + hp, wq_off, hoff);
                epilogue3(acc3b, c1, a_h1 + hq + hrow);
            }
        }
        if (xw && t + 1 < Tn) {
            const unsigned xn = 512u - xc;
            sts_f32(a_xb + xn + 0 * 128 + xl * 4, xp4.x);
            sts_f32(a_xb + xn + 1 * 128 + xl * 4, xp4.y);
            sts_f32(a_xb + xn + 2 * 128 + xl * 4, xp4.z);
            sts_f32(a_xb + xn + 3 * 128 + xl * 4, xp4.w);
        }
        __syncthreads();   // single sync per interval (hazard sets unchanged from R15)
    }

    // ---------- final l1(T-1): reads h1[HBUFB], h0[0]; writes h1[0] ----------
    if (is4) {
        gemv_l1(acc1, b1s, a_q1ih, a_q1hh, a_h0 + 0, a_h1 + HBUFB, wq_off, hoff);
        epilogue(acc1, c1, a_h1 + 0 + hrow);
    } else if (!xw) {
        gemv3_l1(acc3b, b1s, a_q1ih, a_q1hh, a_h0 + 0, a_h1 + HBUFB, wq_off, hoff);
        epilogue3(acc3b, c1, a_h1 + 0 + hrow);
    }
    __syncthreads();

    // ---- final FC: out = fcW @ h1_final + fcb (h1 in buffer 0) ----
    if (tid < TB * Fdim) {
        int b2 = tid >> 2, f = tid & 3;
        float a = fcb[f];
        const float* h1 = sm + (O_H1 / 4);
        #pragma unroll
        for (int j = 0; j < Hn; ++j)
            a = fmaf(fcW[f * Hn + j], h1[j * (HSTR / 4) + b2], a);
        out[((size_t)blockIdx.x * TB + b2) * Fdim + f] = a;
    }
}

extern "C" void kernel_launch(void* const* d_in, const int* in_sizes, int n_in,
                              void* d_out, int out_size) {
    const float* x    = (const float*)d_in[0];
    const float* Wih0 = (const float*)d_in[1];
    const float* Whh0 = (const float*)d_in[2];
    const float* bih0 = (const float*)d_in[3];
    const float* bhh0 = (const float*)d_in[4];
    const float* Wih1 = (const float*)d_in[5];
    const float* Whh1 = (const float*)d_in[6];
    const float* bih1 = (const float*)d_in[7];
    const float* bhh1 = (const float*)d_in[8];
    const float* fcW  = (const float*)d_in[9];
    const float* fcb  = (const float*)d_in[10];
    float* out = (float*)d_out;

    cudaFuncSetAttribute(lstm2_kernel,
                         cudaFuncAttributeMaxDynamicSharedMemorySize, SMEM_BYTES);
    lstm2_kernel<<<Bsz / TB, NT, SMEM_BYTES>>>(
        x, Wih0, Whh0, bih0, bhh0, Wih1, Whh1, bih1, bhh1, fcW, fcb, out);
}